// round 3
// baseline (speedup 1.0000x reference)
#include <cuda_runtime.h>

// out = foldl over T slices: s = (1-lam)*s + lam*adj[t], s0 = adj[0]
// Pure HBM streaming (272 MB @ T=16, N=2048).
// Thread coarsening x4 -> grid=1024 blocks -> single wave on 152 SMs
// (eliminates wave-quantization tail). Recurrence form (bit-exact vs ref).

#ifndef COARSEN
#define COARSEN 4
#endif

template <int T>
__global__ void __launch_bounds__(256, 8)
ema_fold_kernel(const float4* __restrict__ adj,
                const float* __restrict__ lam_p,
                float4* __restrict__ out,
                int n4) {
    const float lam = __ldg(lam_p);
    const float om  = 1.0f - lam;

    // Block owns a contiguous chunk of COARSEN*blockDim float4s.
    int base = blockIdx.x * (256 * COARSEN) + threadIdx.x;

#pragma unroll
    for (int e = 0; e < COARSEN; ++e) {
        int i = base + e * 256;
        if (i < n4) {
            const float4* p = adj + i;
            float4 s = p[0];
#pragma unroll
            for (int t = 1; t < T; ++t) {
                float4 v = p[(size_t)t * (size_t)n4];
                s.x = fmaf(om, s.x, lam * v.x);
                s.y = fmaf(om, s.y, lam * v.y);
                s.z = fmaf(om, s.z, lam * v.z);
                s.w = fmaf(om, s.w, lam * v.w);
            }
            __stcs(out + i, s);
        }
    }
}

// Generic-T fallback (runtime T), grid-stride.
__global__ void __launch_bounds__(256, 8)
ema_fold_generic(const float4* __restrict__ adj,
                 const float* __restrict__ lam_p,
                 float4* __restrict__ out,
                 int n4, int T) {
    const float lam = __ldg(lam_p);
    const float om  = 1.0f - lam;

    for (int i = blockIdx.x * blockDim.x + threadIdx.x; i < n4;
         i += gridDim.x * blockDim.x) {
        const float4* p = adj + i;
        float4 s = p[0];
        for (int t = 1; t < T; ++t) {
            float4 v = p[(size_t)t * (size_t)n4];
            s.x = fmaf(om, s.x, lam * v.x);
            s.y = fmaf(om, s.y, lam * v.y);
            s.z = fmaf(om, s.z, lam * v.z);
            s.w = fmaf(om, s.w, lam * v.w);
        }
        __stcs(out + i, s);
    }
}

extern "C" void kernel_launch(void* const* d_in, const int* in_sizes, int n_in,
                              void* d_out, int out_size) {
    const float4* adj  = (const float4*)d_in[0];
    const float*  lamp = (const float*)d_in[1];
    float4*       out  = (float4*)d_out;

    const int total = in_sizes[0];        // T * N * N
    const int T     = total / out_size;   // leading axis length
    const int n4    = out_size / 4;       // float4 elements per slice

    const int threads = 256;

    if (T == 16) {
        const int blocks = (n4 + threads * COARSEN - 1) / (threads * COARSEN);
        ema_fold_kernel<16><<<blocks, threads>>>(adj, lamp, out, n4);
    } else {
        const int blocks = (n4 + threads - 1) / threads;
        ema_fold_generic<<<blocks, threads>>>(adj, lamp, out, n4, T);
    }
}

// round 4
// speedup vs baseline: 1.0499x; 1.0499x over previous
#include <cuda_runtime.h>

// out = foldl over T slices: s = (1-lam)*s + lam*adj[t], s0 = adj[0]
// Pure HBM streaming (272 MB @ T=16, N=2048) — pinned at the LTS chip cap
// (~6300 B/cyc). Plain LDG.128/STG.128 (streaming hints measured slower),
// grid 4096 x 256, recurrence form (bit-exact vs reference).

template <int T>
__global__ void __launch_bounds__(256, 8)
ema_fold_kernel(const float4* __restrict__ adj,
                const float* __restrict__ lam_p,
                float4* __restrict__ out,
                int n4) {
    int i = blockIdx.x * blockDim.x + threadIdx.x;
    if (i >= n4) return;

    const float lam = __ldg(lam_p);
    const float om  = 1.0f - lam;

    const float4* p = adj + i;
    float4 s = p[0];
#pragma unroll
    for (int t = 1; t < T; ++t) {
        float4 v = p[(size_t)t * (size_t)n4];
        s.x = fmaf(om, s.x, lam * v.x);
        s.y = fmaf(om, s.y, lam * v.y);
        s.z = fmaf(om, s.z, lam * v.z);
        s.w = fmaf(om, s.w, lam * v.w);
    }
    out[i] = s;
}

// Generic-T fallback (runtime T), grid-stride.
__global__ void __launch_bounds__(256, 8)
ema_fold_generic(const float4* __restrict__ adj,
                 const float* __restrict__ lam_p,
                 float4* __restrict__ out,
                 int n4, int T) {
    const float lam = __ldg(lam_p);
    const float om  = 1.0f - lam;

    for (int i = blockIdx.x * blockDim.x + threadIdx.x; i < n4;
         i += gridDim.x * blockDim.x) {
        const float4* p = adj + i;
        float4 s = p[0];
        for (int t = 1; t < T; ++t) {
            float4 v = p[(size_t)t * (size_t)n4];
            s.x = fmaf(om, s.x, lam * v.x);
            s.y = fmaf(om, s.y, lam * v.y);
            s.z = fmaf(om, s.z, lam * v.z);
            s.w = fmaf(om, s.w, lam * v.w);
        }
        out[i] = s;
    }
}

extern "C" void kernel_launch(void* const* d_in, const int* in_sizes, int n_in,
                              void* d_out, int out_size) {
    const float4* adj  = (const float4*)d_in[0];
    const float*  lamp = (const float*)d_in[1];
    float4*       out  = (float4*)d_out;

    const int total = in_sizes[0];        // T * N * N
    const int T     = total / out_size;   // leading axis length
    const int n4    = out_size / 4;       // float4 elements per slice

    const int threads = 256;
    const int blocks  = (n4 + threads - 1) / threads;

    if (T == 16) {
        ema_fold_kernel<16><<<blocks, threads>>>(adj, lamp, out, n4);
    } else {
        ema_fold_generic<<<blocks, threads>>>(adj, lamp, out, n4, T);
    }
}

// round 5
// speedup vs baseline: 1.0506x; 1.0007x over previous
#include <cuda_runtime.h>

// out = (1-lam)^(T-1)*adj[0] + sum_{t>=1} lam*(1-lam)^(T-1-t)*adj[t]
// Pure HBM streaming (272 MB). Explicit front-batched loads: all T LDG.128s
// issued before any FMA -> per-warp MLP=16. No launch-bounds reg cap.

template <int T>
__global__ void __launch_bounds__(256)
ema_fold_kernel(const float4* __restrict__ adj,
                const float* __restrict__ lam_p,
                float4* __restrict__ out,
                int n4) {
    int i = blockIdx.x * blockDim.x + threadIdx.x;
    if (i >= n4) return;

    const float lam = __ldg(lam_p);
    const float om  = 1.0f - lam;

    // Front-batch all T loads (independent -> MLP=T).
    float4 v[T];
    const float4* p = adj + i;
#pragma unroll
    for (int t = 0; t < T; ++t) {
        v[t] = p[(size_t)t * (size_t)n4];
    }

    // Weights: w[t] = lam * om^(T-1-t) for t>=1, w[0] = om^(T-1).
    float w[T];
    float pw = 1.0f;
#pragma unroll
    for (int t = T - 1; t >= 1; --t) { w[t] = lam * pw; pw *= om; }
    w[0] = pw;

    float4 s = make_float4(0.f, 0.f, 0.f, 0.f);
#pragma unroll
    for (int t = 0; t < T; ++t) {
        s.x = fmaf(w[t], v[t].x, s.x);
        s.y = fmaf(w[t], v[t].y, s.y);
        s.z = fmaf(w[t], v[t].z, s.z);
        s.w = fmaf(w[t], v[t].w, s.w);
    }
    out[i] = s;
}

// Generic-T fallback (runtime T), grid-stride, recurrence form.
__global__ void __launch_bounds__(256)
ema_fold_generic(const float4* __restrict__ adj,
                 const float* __restrict__ lam_p,
                 float4* __restrict__ out,
                 int n4, int T) {
    const float lam = __ldg(lam_p);
    const float om  = 1.0f - lam;

    for (int i = blockIdx.x * blockDim.x + threadIdx.x; i < n4;
         i += gridDim.x * blockDim.x) {
        const float4* p = adj + i;
        float4 s = p[0];
        for (int t = 1; t < T; ++t) {
            float4 v = p[(size_t)t * (size_t)n4];
            s.x = fmaf(om, s.x, lam * v.x);
            s.y = fmaf(om, s.y, lam * v.y);
            s.z = fmaf(om, s.z, lam * v.z);
            s.w = fmaf(om, s.w, lam * v.w);
        }
        out[i] = s;
    }
}

extern "C" void kernel_launch(void* const* d_in, const int* in_sizes, int n_in,
                              void* d_out, int out_size) {
    const float4* adj  = (const float4*)d_in[0];
    const float*  lamp = (const float*)d_in[1];
    float4*       out  = (float4*)d_out;

    const int total = in_sizes[0];        // T * N * N
    const int T     = total / out_size;   // leading axis length
    const int n4    = out_size / 4;       // float4 elements per slice

    const int threads = 256;
    const int blocks  = (n4 + threads - 1) / threads;

    if (T == 16) {
        ema_fold_kernel<16><<<blocks, threads>>>(adj, lamp, out, n4);
    } else {
        ema_fold_generic<<<blocks, threads>>>(adj, lamp, out, n4, T);
    }
}